// round 1
// baseline (speedup 1.0000x reference)
#include <cuda_runtime.h>

// Problem constants (fixed shapes: x = (2, 64, 256, 256) fp32, stoken_size = 16)
#define BB   2
#define CC   64
#define HH   256
#define WW   256
#define SS   16
#define NH   16
#define NW   16
#define NSP  256      // nH*nW
#define NPIX 65536    // H*W

// Scratch (device globals; no allocations allowed)
__device__ float g_cent0[BB*NSP*CC];
__device__ float g_csq0 [BB*NSP];
__device__ float g_cent1[BB*NSP*CC];
__device__ float g_csq1 [BB*NSP];
// per-block partials: [b][blk][k(9)][65]  (c=0..63 -> sum w*p[c], c=64 -> sum w)
__device__ float g_part [BB*NSP*9*65];

// ---------------------------------------------------------------------------
// K1: initial centroids = per-16x16-block channel means (+ |c|^2 per block)
// grid = B*nS (512), block = 256 (one thread per pixel of the block)
// ---------------------------------------------------------------------------
__global__ __launch_bounds__(256) void k_means(const float* __restrict__ x)
{
    int bid = blockIdx.x;
    int b   = bid >> 8;
    int blk = bid & 255;
    int sy  = blk >> 4, sx = blk & 15;
    int tid = threadIdx.x;
    int ry  = tid >> 4, rx = tid & 15;
    int n   = (sy*SS + ry)*WW + sx*SS + rx;
    const float* xp = x + (size_t)b*CC*NPIX + n;

    __shared__ float wsum[CC][9];   // [channel][warp], padded to 9 (conflict-free)
    int wid = tid >> 5, lane = tid & 31;

    #pragma unroll
    for (int c = 0; c < CC; c++) {
        float v = xp[(size_t)c*NPIX];
        #pragma unroll
        for (int o = 16; o > 0; o >>= 1) v += __shfl_xor_sync(0xffffffffu, v, o);
        if (lane == 0) wsum[c][wid] = v;
    }
    __syncthreads();

    float sq = 0.f;
    if (tid < CC) {
        float s = 0.f;
        #pragma unroll
        for (int w = 0; w < 8; w++) s += wsum[tid][w];
        float m = s * (1.f/256.f);
        g_cent0[((size_t)(b*NSP + blk))*CC + tid] = m;
        sq = m*m;
    }
    #pragma unroll
    for (int o = 16; o > 0; o >>= 1) sq += __shfl_xor_sync(0xffffffffu, sq, o);
    __shared__ float sqw[8];
    if (lane == 0) sqw[wid] = sq;
    __syncthreads();
    if (tid == 0) {
        float t = 0.f;
        #pragma unroll
        for (int w = 0; w < 8; w++) t += sqw[w];
        g_csq0[b*NSP + blk] = t;
    }
}

// ---------------------------------------------------------------------------
// K2: iteration 0. Per-block: load 9 candidate centroids, compute softmax
// weights for all 256 pixels (logits = 2 p.c - |c|^2, shift-equivalent to -d),
// then compute per-block partial sums  partial[k][c] = sum_pix w[k]*p[c]
// and partial[k][64] = sum_pix w[k]  (register-blocked small matmul in smem).
// grid = 512, block = 256, dynamic smem = 77120 B.
// ---------------------------------------------------------------------------
__global__ __launch_bounds__(256, 2) void k_iter0(const float* __restrict__ x)
{
    extern __shared__ float sm[];
    float4* Psh    = (float4*)sm;            // [16][256] pixel features (channel quads)
    float*  Wsh    = sm + 16*256*4;          // [256][9] weights
    float*  cent_s = Wsh + 256*9;            // [9][64]
    float*  csq_s  = cent_s + 9*64;          // [9]

    int bid = blockIdx.x;
    int b   = bid >> 8;
    int blk = bid & 255;
    int sy  = blk >> 4, sx = blk & 15;
    int tid = threadIdx.x;

    // phase A: stage candidate centroids + |c|^2
    for (int i = tid; i < 9*64; i += 256) {
        int k = i >> 6, c = i & 63;
        int cy = sy + (k/3) - 1, cx = sx + (k%3) - 1;
        float v = 0.f;
        if (cy >= 0 && cy < NH && cx >= 0 && cx < NW)
            v = g_cent0[((size_t)(b*NSP + cy*NW + cx))*CC + c];
        cent_s[i] = v;
    }
    if (tid < 9) {
        int cy = sy + (tid/3) - 1, cx = sx + (tid%3) - 1;
        csq_s[tid] = (cy >= 0 && cy < NH && cx >= 0 && cx < NW)
                     ? g_csq0[b*NSP + cy*NW + cx] : 0.f;
    }
    __syncthreads();

    // phase B: per-pixel dot products + softmax
    int ry = tid >> 4, rx = tid & 15;
    int n  = (sy*SS + ry)*WW + sx*SS + rx;
    const float* xp = x + (size_t)b*CC*NPIX + n;

    float dot[9];
    #pragma unroll
    for (int k = 0; k < 9; k++) dot[k] = 0.f;

    #pragma unroll 4
    for (int c4 = 0; c4 < 16; c4++) {
        float4 p;
        p.x = xp[(size_t)(c4*4 + 0)*NPIX];
        p.y = xp[(size_t)(c4*4 + 1)*NPIX];
        p.z = xp[(size_t)(c4*4 + 2)*NPIX];
        p.w = xp[(size_t)(c4*4 + 3)*NPIX];
        Psh[c4*256 + tid] = p;
        #pragma unroll
        for (int k = 0; k < 9; k++) {
            float4 cv = *(const float4*)(cent_s + k*64 + c4*4);
            dot[k] = fmaf(p.x, cv.x, dot[k]);
            dot[k] = fmaf(p.y, cv.y, dot[k]);
            dot[k] = fmaf(p.z, cv.z, dot[k]);
            dot[k] = fmaf(p.w, cv.w, dot[k]);
        }
    }

    float l[9];
    float m = -1e30f;
    #pragma unroll
    for (int k = 0; k < 9; k++) {
        int cy = sy + (k/3) - 1, cx = sx + (k%3) - 1;
        bool valid = (cy >= 0 && cy < NH && cx >= 0 && cx < NW);
        l[k] = valid ? (2.f*dot[k] - csq_s[k]) : -1e30f;
        m = fmaxf(m, l[k]);
    }
    float e[9], ssum = 0.f;
    #pragma unroll
    for (int k = 0; k < 9; k++) {
        e[k] = (l[k] > -1e29f) ? __expf(l[k] - m) : 0.f;
        ssum += e[k];
    }
    float inv = 1.f / ssum;
    #pragma unroll
    for (int k = 0; k < 9; k++) Wsh[tid*9 + k] = e[k]*inv;

    __syncthreads();

    // phase C: partial[k][c] = sum_pix Wsh[pix][k] * Psh[c][pix]
    if (tid < 144) {
        int k = tid >> 4, c4 = tid & 15;
        float4 acc = make_float4(0.f, 0.f, 0.f, 0.f);
        #pragma unroll 8
        for (int pix = 0; pix < 256; pix++) {
            float  w = Wsh[pix*9 + k];
            float4 p = Psh[c4*256 + pix];
            acc.x = fmaf(w, p.x, acc.x);
            acc.y = fmaf(w, p.y, acc.y);
            acc.z = fmaf(w, p.z, acc.z);
            acc.w = fmaf(w, p.w, acc.w);
        }
        float* dst = g_part + ((size_t)((b*NSP + blk)*9 + k))*65 + c4*4;
        dst[0] = acc.x; dst[1] = acc.y; dst[2] = acc.z; dst[3] = acc.w;
    } else if (tid < 153) {
        int k = tid - 144;
        float s = 0.f;
        #pragma unroll 8
        for (int pix = 0; pix < 256; pix++) s += Wsh[pix*9 + k];
        g_part[((size_t)((b*NSP + blk)*9 + k))*65 + 64] = s;
    }
}

// ---------------------------------------------------------------------------
// K3: gather per-superpixel centroid update (no atomics): superpixel s at
// (sy,sx) receives from neighbor block nb=(sy+dy,sx+dx) at its slot k'=8-j.
// grid = 512 (b,s), block = 64 (one thread per channel)
// ---------------------------------------------------------------------------
__global__ __launch_bounds__(64) void k_update()
{
    int bid = blockIdx.x;
    int b   = bid >> 8;
    int s   = bid & 255;
    int sy  = s >> 4, sx = s & 15;
    int c   = threadIdx.x;

    float num = 0.f, den = 0.f;
    #pragma unroll
    for (int j = 0; j < 9; j++) {
        int dy = j/3 - 1, dx = j%3 - 1;
        int ny = sy + dy, nx = sx + dx;
        if (ny >= 0 && ny < NH && nx >= 0 && nx < NW) {
            int nb = ny*NW + nx;
            const float* p = g_part + ((size_t)((b*NSP + nb)*9 + (8 - j)))*65;
            num += p[c];
            den += p[64];
        }
    }
    float mval = num / (den + 1e-16f);
    g_cent1[((size_t)(b*NSP + s))*CC + c] = mval;

    float sq = mval*mval;
    #pragma unroll
    for (int o = 16; o > 0; o >>= 1) sq += __shfl_xor_sync(0xffffffffu, sq, o);
    __shared__ float t2[2];
    if ((c & 31) == 0) t2[c >> 5] = sq;
    __syncthreads();
    if (c == 0) g_csq1[b*NSP + s] = t2[0] + t2[1];
}

// ---------------------------------------------------------------------------
// K4: iteration 1 (final): recompute weights against updated centroids and
// scatter into the (pre-zeroed) output: out[b][cand_k][n] = w[k].
// grid = 512, block = 256.
// ---------------------------------------------------------------------------
__global__ __launch_bounds__(256) void k_final(const float* __restrict__ x,
                                               float* __restrict__ out)
{
    __shared__ __align__(16) float cent_s[9*64];
    __shared__ float csq_s[9];

    int bid = blockIdx.x;
    int b   = bid >> 8;
    int blk = bid & 255;
    int sy  = blk >> 4, sx = blk & 15;
    int tid = threadIdx.x;

    for (int i = tid; i < 9*64; i += 256) {
        int k = i >> 6, c = i & 63;
        int cy = sy + (k/3) - 1, cx = sx + (k%3) - 1;
        float v = 0.f;
        if (cy >= 0 && cy < NH && cx >= 0 && cx < NW)
            v = g_cent1[((size_t)(b*NSP + cy*NW + cx))*CC + c];
        cent_s[i] = v;
    }
    if (tid < 9) {
        int cy = sy + (tid/3) - 1, cx = sx + (tid%3) - 1;
        csq_s[tid] = (cy >= 0 && cy < NH && cx >= 0 && cx < NW)
                     ? g_csq1[b*NSP + cy*NW + cx] : 0.f;
    }
    __syncthreads();

    int ry = tid >> 4, rx = tid & 15;
    int n  = (sy*SS + ry)*WW + sx*SS + rx;
    const float* xp = x + (size_t)b*CC*NPIX + n;

    float dot[9];
    #pragma unroll
    for (int k = 0; k < 9; k++) dot[k] = 0.f;

    #pragma unroll 4
    for (int c4 = 0; c4 < 16; c4++) {
        float4 p;
        p.x = xp[(size_t)(c4*4 + 0)*NPIX];
        p.y = xp[(size_t)(c4*4 + 1)*NPIX];
        p.z = xp[(size_t)(c4*4 + 2)*NPIX];
        p.w = xp[(size_t)(c4*4 + 3)*NPIX];
        #pragma unroll
        for (int k = 0; k < 9; k++) {
            float4 cv = *(const float4*)(cent_s + k*64 + c4*4);
            dot[k] = fmaf(p.x, cv.x, dot[k]);
            dot[k] = fmaf(p.y, cv.y, dot[k]);
            dot[k] = fmaf(p.z, cv.z, dot[k]);
            dot[k] = fmaf(p.w, cv.w, dot[k]);
        }
    }

    float l[9];
    float m = -1e30f;
    #pragma unroll
    for (int k = 0; k < 9; k++) {
        int cy = sy + (k/3) - 1, cx = sx + (k%3) - 1;
        bool valid = (cy >= 0 && cy < NH && cx >= 0 && cx < NW);
        l[k] = valid ? (2.f*dot[k] - csq_s[k]) : -1e30f;
        m = fmaxf(m, l[k]);
    }
    float e[9], ssum = 0.f;
    #pragma unroll
    for (int k = 0; k < 9; k++) {
        e[k] = (l[k] > -1e29f) ? __expf(l[k] - m) : 0.f;
        ssum += e[k];
    }
    float inv = 1.f / ssum;

    #pragma unroll
    for (int k = 0; k < 9; k++) {
        int cy = sy + (k/3) - 1, cx = sx + (k%3) - 1;
        if (cy >= 0 && cy < NH && cx >= 0 && cx < NW) {
            out[((size_t)(b*NSP + cy*NW + cx) << 16) + n] = e[k]*inv;
        }
    }
}

// ---------------------------------------------------------------------------
extern "C" void kernel_launch(void* const* d_in, const int* in_sizes, int n_in,
                              void* d_out, int out_size)
{
    const float* x = (const float*)d_in[0];
    float* out = (float*)d_out;

    const int smem_bytes = (16*256*4 + 256*9 + 9*64 + 16) * (int)sizeof(float); // 77120

    cudaMemsetAsync(d_out, 0, (size_t)out_size * sizeof(float), 0);
    k_means<<<BB*NSP, 256>>>(x);
    cudaFuncSetAttribute(k_iter0, cudaFuncAttributeMaxDynamicSharedMemorySize, smem_bytes);
    k_iter0<<<BB*NSP, 256, smem_bytes>>>(x);
    k_update<<<BB*NSP, 64>>>();
    k_final<<<BB*NSP, 256>>>(x, out);
}